// round 6
// baseline (speedup 1.0000x reference)
#include <cuda_runtime.h>
#include <cuda_fp16.h>
#include <cstdint>
#include <cstddef>

#define DD   1024
#define HH   4096
#define EE   8
#define NTOK 8192
#define CAP  8192
// smem map (per CTA): 3 A-stages (16KB) | 2 B-buffers (16KB) | toks | wts
#define SMEM_B0   49152
#define SMEM_TOKS 81920
#define SMEM_WTS  82432
#define SMEM_SZ   82944

// ---- device scratch (static: no runtime allocation) ----
__device__ int    g_counts[EE];
__device__ int    g_padded[EE];
__device__ int    g_tokens[EE * CAP];
__device__ float  g_wt[EE * CAP];
__device__ __half g_xh[(size_t)NTOK * DD];          // x fp16, 16MB
__device__ __half g_h[(size_t)EE * CAP * HH];       // relu(h) fp16, 128MB (sparse use)

// ---- helpers ----
__device__ __forceinline__ uint32_t smem_u32(const void* p) {
    uint32_t a;
    asm("{ .reg .u64 t; cvta.to.shared.u64 t, %1; cvt.u32.u64 %0, t; }" : "=r"(a) : "l"(p));
    return a;
}
__device__ __forceinline__ void cp_async16(uint32_t dst, const void* src) {
    asm volatile("cp.async.cg.shared.global [%0], [%1], 16;" :: "r"(dst), "l"(src) : "memory");
}
__device__ __forceinline__ void cp_commit() {
    asm volatile("cp.async.commit_group;" ::: "memory");
}
__device__ __forceinline__ void cp_wait1() {
    asm volatile("cp.async.wait_group 1;" ::: "memory");
}
__device__ __forceinline__ void ldsm4(uint32_t r[4], uint32_t addr) {
    asm volatile("ldmatrix.sync.aligned.m8n8.x4.shared.b16 {%0,%1,%2,%3}, [%4];"
                 : "=r"(r[0]), "=r"(r[1]), "=r"(r[2]), "=r"(r[3]) : "r"(addr));
}
__device__ __forceinline__ void ldsm4t(uint32_t r[4], uint32_t addr) {
    asm volatile("ldmatrix.sync.aligned.m8n8.x4.trans.shared.b16 {%0,%1,%2,%3}, [%4];"
                 : "=r"(r[0]), "=r"(r[1]), "=r"(r[2]), "=r"(r[3]) : "r"(addr));
}
__device__ __forceinline__ void mma16816(float c[4], const uint32_t a[4], uint32_t b0, uint32_t b1) {
    asm volatile(
        "mma.sync.aligned.m16n8k16.row.col.f32.f16.f16.f32 "
        "{%0,%1,%2,%3},{%4,%5,%6,%7},{%8,%9},{%0,%1,%2,%3};"
        : "+f"(c[0]), "+f"(c[1]), "+f"(c[2]), "+f"(c[3])
        : "r"(a[0]), "r"(a[1]), "r"(a[2]), "r"(a[3]), "r"(b0), "r"(b1));
}

// ---- zero output + counters (must run before router) ----
__global__ void k_zero(float* __restrict__ out) {
    size_t n4 = (size_t)NTOK * DD / 4;
    float4 z = make_float4(0.f, 0.f, 0.f, 0.f);
    for (size_t j = (size_t)blockIdx.x * blockDim.x + threadIdx.x; j < n4;
         j += (size_t)gridDim.x * blockDim.x)
        reinterpret_cast<float4*>(out)[j] = z;
    if (blockIdx.x == 0 && threadIdx.x < EE) g_counts[threadIdx.x] = 0;
}

// ---- streaming fp32 -> fp16 convert of x ----
__global__ void k_cvt(const float* __restrict__ src, __half* __restrict__ dst) {
    size_t i = ((size_t)blockIdx.x * blockDim.x + threadIdx.x) * 8;
    float4 a = *reinterpret_cast<const float4*>(src + i);
    float4 b = *reinterpret_cast<const float4*>(src + i + 4);
    __half2 h[4];
    h[0] = __floats2half2_rn(a.x, a.y);
    h[1] = __floats2half2_rn(a.z, a.w);
    h[2] = __floats2half2_rn(b.x, b.y);
    h[3] = __floats2half2_rn(b.z, b.w);
    *reinterpret_cast<uint4*>(dst + i) = *reinterpret_cast<uint4*>(h);
}

// ---- router (1 warp per token, fp32 selection) ----
__global__ void k_router(const float* __restrict__ xs, const float* __restrict__ gw) {
    int warp = (int)((blockIdx.x * blockDim.x + threadIdx.x) >> 5);
    int lane = threadIdx.x & 31;
    if (warp >= NTOK) return;

    const float* x = xs + (size_t)warp * DD;
    float xr[32];
#pragma unroll
    for (int i = 0; i < 32; i++) xr[i] = x[lane + 32 * i];

    float logit[EE];
#pragma unroll
    for (int e = 0; e < EE; e++) {
        const float* g = gw + e * DD;
        float a = 0.f;
#pragma unroll
        for (int i = 0; i < 32; i++) a += xr[i] * g[lane + 32 * i];
#pragma unroll
        for (int o = 16; o; o >>= 1) a += __shfl_xor_sync(0xFFFFFFFFu, a, o);
        logit[e] = a;
    }

    if (lane == 0) {
        float v0 = -1e30f, v1 = -1e30f;
        int i0 = 0, i1 = 0;
#pragma unroll
        for (int e = 0; e < EE; e++) {
            float v = logit[e];
            if (v > v0) { v1 = v0; i1 = i0; v0 = v; i0 = e; }
            else if (v > v1) { v1 = v; i1 = e; }
        }
        float e1 = __expf(v1 - v0);
        float s = 1.f + e1;
        float w0 = 1.f / s;
        float w1 = e1 / s;

        int s0 = atomicAdd(&g_counts[i0], 1);
        g_tokens[i0 * CAP + s0] = warp;
        g_wt[i0 * CAP + s0] = w0;
        int s1 = atomicAdd(&g_counts[i1], 1);
        g_tokens[i1 * CAP + s1] = warp;
        g_wt[i1 * CAP + s1] = w1;
    }
}

// ---- pad each expert list to multiple of 128 with weight-0 dummies ----
__global__ void k_pad() {
    int e = threadIdx.x >> 5;
    int lane = threadIdx.x & 31;
    if (e < EE) {
        int c = g_counts[e];
        if (c > CAP) c = CAP;
        int p = (c + 127) & ~127;
        if (p > CAP) p = CAP;
        for (int s = c + lane; s < p; s += 32) {
            g_tokens[e * CAP + s] = 0;
            g_wt[e * CAP + s] = 0.f;
        }
        if (lane == 0) g_padded[e] = p;
    }
}

// ---- fp16 tensor-core grouped GEMM, fused fp32->fp16 B conversion ----
// CTA tile 128x128, BK=64, 4 warps (2x2), warp tile 64x64.
// A (fp16 in gmem): 3-stage cp.async.  B (fp32 weights): LDG->cvt->STS, 2 buffers.
// IS1:  h[e,slot][n] = relu(sum_k x[tok][k] * w1[e][k][n]),   K=DD, Bstride=HH
// !IS1: out[tok][n] += wt * sum_k h[e,slot][k] * w2[e][k][n], K=HH, Bstride=DD
template <bool IS1>
__global__ __launch_bounds__(128, 2) void k_gemm(const float* __restrict__ w,
                                                 float* __restrict__ out) {
    const int e = blockIdx.z;
    const int m0 = blockIdx.y * 128;
    if (m0 >= g_padded[e]) return;
    const int n0 = blockIdx.x * 128;
    const int KDIM = IS1 ? DD : HH;
    const int BSTR = IS1 ? HH : DD;
    const int T = KDIM / 64;

    extern __shared__ char smem[];
    const uint32_t sb = smem_u32(smem);
    int* toks = (int*)(smem + SMEM_TOKS);
    float* wts = (float*)(smem + SMEM_WTS);
    const int tid = threadIdx.x;

    {
        toks[tid] = g_tokens[e * CAP + m0 + tid];
        if (!IS1) wts[tid] = g_wt[e * CAP + m0 + tid];
    }
    __syncthreads();

    const float* bsrc = w + (size_t)e * DD * HH + n0;   // fp32 weights, natural layout
    const __half* asrc0 = g_h + (size_t)(e * CAP + m0) * HH;  // !IS1 A base

    // A stage: 128 rows x 64 halfs (8 x 16B chunks per row), XOR swizzle
    auto issueA = [&](int kt) {
        const uint32_t Ab = sb + (kt % 3) * 16384;
        const int k0 = kt * 64;
#pragma unroll
        for (int i = 0; i < 8; i++) {
            int idx = tid + 128 * i;
            int row = idx >> 3, c = idx & 7;
            const __half* sa = IS1 ? g_xh + (size_t)toks[row] * DD + k0 + c * 8
                                   : asrc0 + (size_t)row * HH + k0 + c * 8;
            cp_async16(Ab + row * 128 + ((c ^ (row & 7)) << 4), sa);
        }
    };

    // B stage: 64 k-rows x 128 n-cols fp32 -> fp16 smem [row*256B], XOR swizzle.
    // Per thread: 8 x {2 LDG.128 fp32, cvt, 1 STS.128}.
    auto stageB = [&](int kt) {
        const uint32_t Bb = sb + SMEM_B0 + (kt & 1) * 16384;
        const int k0 = kt * 64;
#pragma unroll
        for (int i = 0; i < 8; i++) {
            int j = tid + 128 * i;
            int row = j >> 4, cp = j & 15;   // 16 chunks of 8 cols per row
            const float* s = bsrc + (size_t)(k0 + row) * BSTR + cp * 8;
            float4 v0 = *reinterpret_cast<const float4*>(s);
            float4 v1 = *reinterpret_cast<const float4*>(s + 4);
            __half2 h[4];
            h[0] = __floats2half2_rn(v0.x, v0.y);
            h[1] = __floats2half2_rn(v0.z, v0.w);
            h[2] = __floats2half2_rn(v1.x, v1.y);
            h[3] = __floats2half2_rn(v1.z, v1.w);
            *reinterpret_cast<uint4*>(smem + (Bb - sb) + row * 256 + ((cp ^ (row & 7)) << 4)) =
                *reinterpret_cast<uint4*>(h);
        }
    };

    issueA(0); cp_commit();
    issueA(1); cp_commit();
    stageB(0);

    const int lane = tid & 31, wid = tid >> 5;
    const int wm = wid & 1, wn = wid >> 1;  // 2x2 warps, 64x64 each
    const int lrow = lane & 15, lk = lane >> 4;

    float acc[4][8][4];
#pragma unroll
    for (int a = 0; a < 4; a++)
#pragma unroll
        for (int b = 0; b < 8; b++)
#pragma unroll
            for (int c = 0; c < 4; c++) acc[a][b][c] = 0.f;

    for (int kt = 0; kt < T; kt++) {
        cp_wait1();
        __syncthreads();           // A(kt) landed; B(kt) STS visible
        if (kt + 2 < T) issueA(kt + 2);
        cp_commit();

        const uint32_t Ab = sb + (kt % 3) * 16384;
        const uint32_t Bb = sb + SMEM_B0 + (kt & 1) * 16384;
#pragma unroll
        for (int ks = 0; ks < 4; ks++) {
            uint32_t a[4][4], b[4][4];
#pragma unroll
            for (int mt = 0; mt < 4; mt++) {
                int row = wm * 64 + mt * 16 + lrow;
                ldsm4(a[mt], Ab + row * 128 + ((((ks << 1) | lk) ^ (row & 7)) << 4));
            }
#pragma unroll
            for (int nt2 = 0; nt2 < 4; nt2++) {
                int krow = ks * 16 + lrow;
                int chunk = wn * 8 + nt2 * 2 + lk;
                ldsm4t(b[nt2], Bb + krow * 256 + ((chunk ^ (krow & 7)) << 4));
            }
#pragma unroll
            for (int mt = 0; mt < 4; mt++)
#pragma unroll
                for (int nt = 0; nt < 8; nt++) {
                    const int nt2 = nt >> 1, sub = nt & 1;
                    mma16816(acc[mt][nt], a[mt], b[nt2][2 * sub], b[nt2][2 * sub + 1]);
                }
        }
        if (kt + 1 < T) stageB(kt + 1);  // into the free buffer; visible after next sync
    }

    // epilogue
    const int g = lane >> 2, tg = lane & 3;
    if (IS1) {
#pragma unroll
        for (int mt = 0; mt < 4; mt++) {
            const size_t r0 = (size_t)(e * CAP + m0 + wm * 64 + mt * 16 + g);
            __half* p0 = g_h + r0 * HH + n0;
            __half* p1 = p0 + (size_t)8 * HH;
#pragma unroll
            for (int nt = 0; nt < 8; nt++) {
                const int c = wn * 64 + nt * 8 + tg * 2;
                const float* A = acc[mt][nt];
                *(__half2*)(p0 + c) = __floats2half2_rn(fmaxf(A[0], 0.f), fmaxf(A[1], 0.f));
                *(__half2*)(p1 + c) = __floats2half2_rn(fmaxf(A[2], 0.f), fmaxf(A[3], 0.f));
            }
        }
    } else {
#pragma unroll
        for (int mt = 0; mt < 4; mt++) {
            const int rl = wm * 64 + mt * 16 + g;
            const int t0 = toks[rl];
            const float w0 = wts[rl];
            const int t1 = toks[rl + 8];
            const float w1v = wts[rl + 8];
            float* o0 = out + (size_t)t0 * DD + n0;
            float* o1 = out + (size_t)t1 * DD + n0;
#pragma unroll
            for (int nt = 0; nt < 8; nt++) {
                const int c = wn * 64 + nt * 8 + tg * 2;
                const float* A = acc[mt][nt];
                atomicAdd(o0 + c,     w0 * A[0]);
                atomicAdd(o0 + c + 1, w0 * A[1]);
                atomicAdd(o1 + c,     w1v * A[2]);
                atomicAdd(o1 + c + 1, w1v * A[3]);
            }
        }
    }
}

extern "C" void kernel_launch(void* const* d_in, const int* in_sizes, int n_in,
                              void* d_out, int out_size) {
    const float* xs = (const float*)d_in[0];
    const float* gw = (const float*)d_in[1];
    const float* w1 = (const float*)d_in[2];
    const float* w2 = (const float*)d_in[3];
    float* out = (float*)d_out;

    cudaFuncSetAttribute(k_gemm<true>, cudaFuncAttributeMaxDynamicSharedMemorySize, SMEM_SZ);
    cudaFuncSetAttribute(k_gemm<false>, cudaFuncAttributeMaxDynamicSharedMemorySize, SMEM_SZ);

    __half* xh; cudaGetSymbolAddress((void**)&xh, g_xh);

    k_zero<<<2048, 256>>>(out);              // out=0 + counters=0 (before router)
    k_cvt<<<(NTOK * DD / 8) / 256, 256>>>(xs, xh);
    k_router<<<NTOK / 8, 256>>>(xs, gw);
    k_pad<<<1, 256>>>();

    k_gemm<true><<<dim3(HH / 128, CAP / 128, EE), 128, SMEM_SZ>>>(w1, out);
    k_gemm<false><<<dim3(DD / 128, CAP / 128, EE), 128, SMEM_SZ>>>(w2, out);
}

// round 7
// speedup vs baseline: 1.2755x; 1.2755x over previous
#include <cuda_runtime.h>
#include <cuda_fp16.h>
#include <cstdint>
#include <cstddef>

#define DD   1024
#define HH   4096
#define EE   8
#define NTOK 8192
#define CAP  8192
#define NSTAGE 3
#define STAGE_BYTES 32768            // 16KB A (128m x 64k) + 16KB B (64k x 128n)
#define SMEM_TOKS (NSTAGE * STAGE_BYTES)
#define SMEM_WTS  (SMEM_TOKS + 512)
#define SMEM_SZ   (SMEM_WTS + 512)   // 99328 bytes

#define NX ((size_t)NTOK * DD)       // 8388608
#define NW ((size_t)EE * DD * HH)    // 33554432

// ---- device scratch (static: no runtime allocation) ----
__device__ int    g_counts[EE];
__device__ int    g_tokens[EE * CAP];
__device__ float  g_wt[EE * CAP];
__device__ __half g_xh[NX];                         // x fp16, 16MB
__device__ __half g_w1h[NW];                        // w1 fp16 [e][d][h], 64MB
__device__ __half g_w2h[NW];                        // w2 fp16 [e][h][d], 64MB
__device__ __half g_h[(size_t)EE * CAP * HH];       // relu(h) fp16, 128MB (sparse use)

// ---- helpers ----
__device__ __forceinline__ uint32_t smem_u32(const void* p) {
    uint32_t a;
    asm("{ .reg .u64 t; cvta.to.shared.u64 t, %1; cvt.u32.u64 %0, t; }" : "=r"(a) : "l"(p));
    return a;
}
__device__ __forceinline__ void cp_async16(uint32_t dst, const void* src) {
    asm volatile("cp.async.cg.shared.global [%0], [%1], 16;" :: "r"(dst), "l"(src) : "memory");
}
__device__ __forceinline__ void cp_commit() {
    asm volatile("cp.async.commit_group;" ::: "memory");
}
__device__ __forceinline__ void cp_wait1() {
    asm volatile("cp.async.wait_group 1;" ::: "memory");
}
__device__ __forceinline__ void ldsm4(uint32_t r[4], uint32_t addr) {
    asm volatile("ldmatrix.sync.aligned.m8n8.x4.shared.b16 {%0,%1,%2,%3}, [%4];"
                 : "=r"(r[0]), "=r"(r[1]), "=r"(r[2]), "=r"(r[3]) : "r"(addr));
}
__device__ __forceinline__ void ldsm4t(uint32_t r[4], uint32_t addr) {
    asm volatile("ldmatrix.sync.aligned.m8n8.x4.trans.shared.b16 {%0,%1,%2,%3}, [%4];"
                 : "=r"(r[0]), "=r"(r[1]), "=r"(r[2]), "=r"(r[3]) : "r"(addr));
}
__device__ __forceinline__ void mma16816(float c[4], const uint32_t a[4], uint32_t b0, uint32_t b1) {
    asm volatile(
        "mma.sync.aligned.m16n8k16.row.col.f32.f16.f16.f32 "
        "{%0,%1,%2,%3},{%4,%5,%6,%7},{%8,%9},{%0,%1,%2,%3};"
        : "+f"(c[0]), "+f"(c[1]), "+f"(c[2]), "+f"(c[3])
        : "r"(a[0]), "r"(a[1]), "r"(a[2]), "r"(a[3]), "r"(b0), "r"(b1));
}

// ---- zero output + token lists + weights + counters ----
__global__ void k_zero(float* __restrict__ out) {
    size_t n4 = (size_t)NTOK * DD / 4;             // out, in float4
    float4 z = make_float4(0.f, 0.f, 0.f, 0.f);
    for (size_t j = (size_t)blockIdx.x * blockDim.x + threadIdx.x; j < n4;
         j += (size_t)gridDim.x * blockDim.x)
        reinterpret_cast<float4*>(out)[j] = z;
    size_t nt4 = (size_t)EE * CAP / 4;             // tokens + wt, in int4
    for (size_t j = (size_t)blockIdx.x * blockDim.x + threadIdx.x; j < nt4;
         j += (size_t)gridDim.x * blockDim.x) {
        reinterpret_cast<int4*>(g_tokens)[j] = make_int4(0, 0, 0, 0);
        reinterpret_cast<float4*>(g_wt)[j] = z;
    }
    if (blockIdx.x == 0 && threadIdx.x < EE) g_counts[threadIdx.x] = 0;
}

// ---- one-shot fp32->fp16 convert of x, w1, w2 ----
__global__ void k_cvt_all(const float* __restrict__ xs, const float* __restrict__ w1,
                          const float* __restrict__ w2) {
    size_t i = ((size_t)blockIdx.x * blockDim.x + threadIdx.x) * 8;
    const float* src;
    __half* dst;
    size_t off;
    if (i < NX)            { src = xs; dst = g_xh;  off = i; }
    else if (i < NX + NW)  { src = w1; dst = g_w1h; off = i - NX; }
    else                   { src = w2; dst = g_w2h; off = i - NX - NW; }
    float4 a = *reinterpret_cast<const float4*>(src + off);
    float4 b = *reinterpret_cast<const float4*>(src + off + 4);
    __half2 h[4];
    h[0] = __floats2half2_rn(a.x, a.y);
    h[1] = __floats2half2_rn(a.z, a.w);
    h[2] = __floats2half2_rn(b.x, b.y);
    h[3] = __floats2half2_rn(b.z, b.w);
    *reinterpret_cast<uint4*>(dst + off) = *reinterpret_cast<uint4*>(h);
}

// ---- router (1 warp per token, fp32 selection) ----
__global__ void k_router(const float* __restrict__ xs, const float* __restrict__ gw) {
    int warp = (int)((blockIdx.x * blockDim.x + threadIdx.x) >> 5);
    int lane = threadIdx.x & 31;
    if (warp >= NTOK) return;

    const float* x = xs + (size_t)warp * DD;
    float xr[32];
#pragma unroll
    for (int i = 0; i < 32; i++) xr[i] = x[lane + 32 * i];

    float logit[EE];
#pragma unroll
    for (int e = 0; e < EE; e++) {
        const float* g = gw + e * DD;
        float a = 0.f;
#pragma unroll
        for (int i = 0; i < 32; i++) a += xr[i] * g[lane + 32 * i];
#pragma unroll
        for (int o = 16; o; o >>= 1) a += __shfl_xor_sync(0xFFFFFFFFu, a, o);
        logit[e] = a;
    }

    if (lane == 0) {
        float v0 = -1e30f, v1 = -1e30f;
        int i0 = 0, i1 = 0;
#pragma unroll
        for (int e = 0; e < EE; e++) {
            float v = logit[e];
            if (v > v0) { v1 = v0; i1 = i0; v0 = v; i0 = e; }
            else if (v > v1) { v1 = v; i1 = e; }
        }
        float e1 = __expf(v1 - v0);
        float s = 1.f + e1;
        float w0 = 1.f / s;
        float w1 = e1 / s;

        int s0 = atomicAdd(&g_counts[i0], 1);
        g_tokens[i0 * CAP + s0] = warp;
        g_wt[i0 * CAP + s0] = w0;
        int s1 = atomicAdd(&g_counts[i1], 1);
        g_tokens[i1 * CAP + s1] = warp;
        g_wt[i1 * CAP + s1] = w1;
    }
}

// ---- fp16 tensor-core grouped GEMM (R4 structure, padded bound from g_counts) ----
// CTA tile 128x128, BK=64, 3-stage cp.async, 4 warps (2x2), warp tile 64x64.
// A: [m][k] smem, ldmatrix.  B: [k][n] smem (natural weight layout), ldmatrix.trans.
// IS1:  h[e,slot][n] = relu(sum_k x[tok][k] * w1[e][k][n]),   K=DD, Bstride=HH
// !IS1: out[tok][n] += wt * sum_k h[e,slot][k] * w2[e][k][n], K=HH, Bstride=DD
template <bool IS1>
__global__ __launch_bounds__(128, 2) void k_gemm(float* __restrict__ out) {
    const int e = blockIdx.z;
    const int m0 = blockIdx.y * 128;
    {
        int c = g_counts[e];
        if (c > CAP) c = CAP;
        int p = (c + 127) & ~127;
        if (p > CAP) p = CAP;
        if (m0 >= p) return;
    }
    const int n0 = blockIdx.x * 128;
    const int KDIM = IS1 ? DD : HH;
    const int BSTR = IS1 ? HH : DD;
    const int T = KDIM / 64;

    extern __shared__ char smem[];
    const uint32_t sb = smem_u32(smem);
    int* toks = (int*)(smem + SMEM_TOKS);
    float* wts = (float*)(smem + SMEM_WTS);
    const int tid = threadIdx.x;

    {
        toks[tid] = g_tokens[e * CAP + m0 + tid];
        if (!IS1) wts[tid] = g_wt[e * CAP + m0 + tid];
    }
    __syncthreads();

    const __half* bsrc = IS1 ? g_w1h + (size_t)e * DD * HH + n0
                             : g_w2h + (size_t)e * HH * DD + n0;
    const __half* asrc0 = g_h + (size_t)(e * CAP + m0) * HH;  // !IS1 A base

    auto issue = [&](int kt) {
        const int s = kt % NSTAGE;
        const int k0 = kt * 64;
        const uint32_t Ab = sb + s * STAGE_BYTES;
        const uint32_t Bb = Ab + 16384;
#pragma unroll
        for (int i = 0; i < 8; i++) {
            int idx = tid + 128 * i;
            int row = idx >> 3, c = idx & 7;
            const __half* sa = IS1 ? g_xh + (size_t)toks[row] * DD + k0 + c * 8
                                   : asrc0 + (size_t)row * HH + k0 + c * 8;
            cp_async16(Ab + row * 128 + ((c ^ (row & 7)) << 4), sa);
        }
#pragma unroll
        for (int i = 0; i < 8; i++) {
            int idx = tid + 128 * i;
            int row = idx >> 4, c = idx & 15;
            cp_async16(Bb + row * 256 + ((c ^ (row & 7)) << 4),
                       bsrc + (size_t)(k0 + row) * BSTR + c * 8);
        }
    };

    issue(0); cp_commit();
    issue(1); cp_commit();

    const int lane = tid & 31, wid = tid >> 5;
    const int wm = wid & 1, wn = wid >> 1;  // 2x2 warps, 64x64 each
    const int lrow = lane & 15, lk = lane >> 4;

    float acc[4][8][4];
#pragma unroll
    for (int a = 0; a < 4; a++)
#pragma unroll
        for (int b = 0; b < 8; b++)
#pragma unroll
            for (int c = 0; c < 4; c++) acc[a][b][c] = 0.f;

    for (int kt = 0; kt < T; kt++) {
        cp_wait1();
        __syncthreads();
        if (kt + 2 < T) issue(kt + 2);
        cp_commit();

        const uint32_t Ab = sb + (kt % NSTAGE) * STAGE_BYTES;
        const uint32_t Bb = Ab + 16384;
#pragma unroll
        for (int ks = 0; ks < 4; ks++) {
            uint32_t a[4][4], b[4][4];
#pragma unroll
            for (int mt = 0; mt < 4; mt++) {
                int row = wm * 64 + mt * 16 + lrow;
                ldsm4(a[mt], Ab + row * 128 + ((((ks << 1) | lk) ^ (row & 7)) << 4));
            }
#pragma unroll
            for (int nt2 = 0; nt2 < 4; nt2++) {
                int krow = ks * 16 + lrow;
                int chunk = wn * 8 + nt2 * 2 + lk;
                ldsm4t(b[nt2], Bb + krow * 256 + ((chunk ^ (krow & 7)) << 4));
            }
#pragma unroll
            for (int mt = 0; mt < 4; mt++)
#pragma unroll
                for (int nt = 0; nt < 8; nt++) {
                    const int nt2 = nt >> 1, sub = nt & 1;
                    mma16816(acc[mt][nt], a[mt], b[nt2][2 * sub], b[nt2][2 * sub + 1]);
                }
        }
    }

    // epilogue
    const int g = lane >> 2, tg = lane & 3;
    if (IS1) {
#pragma unroll
        for (int mt = 0; mt < 4; mt++) {
            const size_t r0 = (size_t)(e * CAP + m0 + wm * 64 + mt * 16 + g);
            __half* p0 = g_h + r0 * HH + n0;
            __half* p1 = p0 + (size_t)8 * HH;
#pragma unroll
            for (int nt = 0; nt < 8; nt++) {
                const int c = wn * 64 + nt * 8 + tg * 2;
                const float* A = acc[mt][nt];
                *(__half2*)(p0 + c) = __floats2half2_rn(fmaxf(A[0], 0.f), fmaxf(A[1], 0.f));
                *(__half2*)(p1 + c) = __floats2half2_rn(fmaxf(A[2], 0.f), fmaxf(A[3], 0.f));
            }
        }
    } else {
#pragma unroll
        for (int mt = 0; mt < 4; mt++) {
            const int rl = wm * 64 + mt * 16 + g;
            const int t0 = toks[rl];
            const float w0 = wts[rl];
            const int t1 = toks[rl + 8];
            const float w1v = wts[rl + 8];
            float* o0 = out + (size_t)t0 * DD + n0;
            float* o1 = out + (size_t)t1 * DD + n0;
#pragma unroll
            for (int nt = 0; nt < 8; nt++) {
                const int c = wn * 64 + nt * 8 + tg * 2;
                const float* A = acc[mt][nt];
                atomicAdd(o0 + c,     w0 * A[0]);
                atomicAdd(o0 + c + 1, w0 * A[1]);
                atomicAdd(o1 + c,     w1v * A[2]);
                atomicAdd(o1 + c + 1, w1v * A[3]);
            }
        }
    }
}

extern "C" void kernel_launch(void* const* d_in, const int* in_sizes, int n_in,
                              void* d_out, int out_size) {
    const float* xs = (const float*)d_in[0];
    const float* gw = (const float*)d_in[1];
    const float* w1 = (const float*)d_in[2];
    const float* w2 = (const float*)d_in[3];
    float* out = (float*)d_out;

    cudaFuncSetAttribute(k_gemm<true>, cudaFuncAttributeMaxDynamicSharedMemorySize, SMEM_SZ);
    cudaFuncSetAttribute(k_gemm<false>, cudaFuncAttributeMaxDynamicSharedMemorySize, SMEM_SZ);

    // launch #1: zero out + token lists + weights + counters
    k_zero<<<2048, 256>>>(out);
    // launch #2: convert x, w1, w2 to fp16 in one pass
    k_cvt_all<<<(int)((NX + 2 * NW) / 8 / 256), 256>>>(xs, w1, w2);
    // launch #3: router
    k_router<<<NTOK / 8, 256>>>(xs, gw);
    // launch #4: gemm1  (ncu capture slot)
    k_gemm<true><<<dim3(HH / 128, CAP / 128, EE), 128, SMEM_SZ>>>(out);
    // launch #5: gemm2
    k_gemm<false><<<dim3(DD / 128, CAP / 128, EE), 128, SMEM_SZ>>>(out);
}

// round 8
// speedup vs baseline: 1.3065x; 1.0243x over previous
#include <cuda_runtime.h>
#include <cuda_fp16.h>
#include <cstdint>
#include <cstddef>

#define DD   1024
#define HH   4096
#define EE   8
#define NTOK 8192
#define CAP  8192
#define NSTAGE 3
#define STAGE_BYTES 32768            // 16KB A (128m x 64k) + 16KB B (64k x 128n)
#define SMEM_TOKS (NSTAGE * STAGE_BYTES)
#define SMEM_WTS  (SMEM_TOKS + 512)
#define SMEM_SZ   (SMEM_WTS + 512)   // 99328 bytes

#define NX ((size_t)NTOK * DD)       // 8388608
#define NW ((size_t)EE * DD * HH)    // 33554432

// ---- device scratch (static: no runtime allocation) ----
__device__ int    g_counts[EE];
__device__ int    g_tokens[EE * CAP];
__device__ float  g_wt[EE * CAP];
__device__ __half g_xh[NX];                         // x fp16, 16MB
__device__ __half g_w1h[NW];                        // w1 fp16 [e][d][h], 64MB
__device__ __half g_w2h[NW];                        // w2 fp16 [e][h][d], 64MB
__device__ __half g_h[(size_t)EE * CAP * HH];       // relu(h) fp16, 128MB (sparse use)

// ---- helpers ----
__device__ __forceinline__ uint32_t smem_u32(const void* p) {
    uint32_t a;
    asm("{ .reg .u64 t; cvta.to.shared.u64 t, %1; cvt.u32.u64 %0, t; }" : "=r"(a) : "l"(p));
    return a;
}
__device__ __forceinline__ void cp_async16(uint32_t dst, const void* src) {
    asm volatile("cp.async.cg.shared.global [%0], [%1], 16;" :: "r"(dst), "l"(src) : "memory");
}
__device__ __forceinline__ void cp_commit() {
    asm volatile("cp.async.commit_group;" ::: "memory");
}
__device__ __forceinline__ void cp_wait1() {
    asm volatile("cp.async.wait_group 1;" ::: "memory");
}
__device__ __forceinline__ void ldsm4(uint32_t r[4], uint32_t addr) {
    asm volatile("ldmatrix.sync.aligned.m8n8.x4.shared.b16 {%0,%1,%2,%3}, [%4];"
                 : "=r"(r[0]), "=r"(r[1]), "=r"(r[2]), "=r"(r[3]) : "r"(addr));
}
__device__ __forceinline__ void ldsm4t(uint32_t r[4], uint32_t addr) {
    asm volatile("ldmatrix.sync.aligned.m8n8.x4.trans.shared.b16 {%0,%1,%2,%3}, [%4];"
                 : "=r"(r[0]), "=r"(r[1]), "=r"(r[2]), "=r"(r[3]) : "r"(addr));
}
__device__ __forceinline__ void mma16816(float c[4], const uint32_t a[4], uint32_t b0, uint32_t b1) {
    asm volatile(
        "mma.sync.aligned.m16n8k16.row.col.f32.f16.f16.f32 "
        "{%0,%1,%2,%3},{%4,%5,%6,%7},{%8,%9},{%0,%1,%2,%3};"
        : "+f"(c[0]), "+f"(c[1]), "+f"(c[2]), "+f"(c[3])
        : "r"(a[0]), "r"(a[1]), "r"(a[2]), "r"(a[3]), "r"(b0), "r"(b1));
}

// ---- zero output + token lists + weights + counters ----
__global__ void k_zero(float* __restrict__ out) {
    size_t n4 = (size_t)NTOK * DD / 4;             // out, in float4
    float4 z = make_float4(0.f, 0.f, 0.f, 0.f);
    for (size_t j = (size_t)blockIdx.x * blockDim.x + threadIdx.x; j < n4;
         j += (size_t)gridDim.x * blockDim.x)
        reinterpret_cast<float4*>(out)[j] = z;
    size_t nt4 = (size_t)EE * CAP / 4;             // tokens + wt, in int4
    for (size_t j = (size_t)blockIdx.x * blockDim.x + threadIdx.x; j < nt4;
         j += (size_t)gridDim.x * blockDim.x) {
        reinterpret_cast<int4*>(g_tokens)[j] = make_int4(0, 0, 0, 0);
        reinterpret_cast<float4*>(g_wt)[j] = z;
    }
    if (blockIdx.x == 0 && threadIdx.x < EE) g_counts[threadIdx.x] = 0;
}

// ---- one-shot fp32->fp16 convert of x, w1, w2 ----
__global__ void k_cvt_all(const float* __restrict__ xs, const float* __restrict__ w1,
                          const float* __restrict__ w2) {
    size_t i = ((size_t)blockIdx.x * blockDim.x + threadIdx.x) * 8;
    const float* src;
    __half* dst;
    size_t off;
    if (i < NX)            { src = xs; dst = g_xh;  off = i; }
    else if (i < NX + NW)  { src = w1; dst = g_w1h; off = i - NX; }
    else                   { src = w2; dst = g_w2h; off = i - NX - NW; }
    float4 a = *reinterpret_cast<const float4*>(src + off);
    float4 b = *reinterpret_cast<const float4*>(src + off + 4);
    __half2 h[4];
    h[0] = __floats2half2_rn(a.x, a.y);
    h[1] = __floats2half2_rn(a.z, a.w);
    h[2] = __floats2half2_rn(b.x, b.y);
    h[3] = __floats2half2_rn(b.z, b.w);
    *reinterpret_cast<uint4*>(dst + off) = *reinterpret_cast<uint4*>(h);
}

// ---- router (1 warp per token, fp32 selection) ----
__global__ void k_router(const float* __restrict__ xs, const float* __restrict__ gw) {
    int warp = (int)((blockIdx.x * blockDim.x + threadIdx.x) >> 5);
    int lane = threadIdx.x & 31;
    if (warp >= NTOK) return;

    const float* x = xs + (size_t)warp * DD;
    float xr[32];
#pragma unroll
    for (int i = 0; i < 32; i++) xr[i] = x[lane + 32 * i];

    float logit[EE];
#pragma unroll
    for (int e = 0; e < EE; e++) {
        const float* g = gw + e * DD;
        float a = 0.f;
#pragma unroll
        for (int i = 0; i < 32; i++) a += xr[i] * g[lane + 32 * i];
#pragma unroll
        for (int o = 16; o; o >>= 1) a += __shfl_xor_sync(0xFFFFFFFFu, a, o);
        logit[e] = a;
    }

    if (lane == 0) {
        float v0 = -1e30f, v1 = -1e30f;
        int i0 = 0, i1 = 0;
#pragma unroll
        for (int e = 0; e < EE; e++) {
            float v = logit[e];
            if (v > v0) { v1 = v0; i1 = i0; v0 = v; i0 = e; }
            else if (v > v1) { v1 = v; i1 = e; }
        }
        float e1 = __expf(v1 - v0);
        float s = 1.f + e1;
        float w0 = 1.f / s;
        float w1 = e1 / s;

        int s0 = atomicAdd(&g_counts[i0], 1);
        g_tokens[i0 * CAP + s0] = warp;
        g_wt[i0 * CAP + s0] = w0;
        int s1 = atomicAdd(&g_counts[i1], 1);
        g_tokens[i1 * CAP + s1] = warp;
        g_wt[i1 * CAP + s1] = w1;
    }
}

// ---- fp16 tensor-core grouped GEMM ----
// CTA tile 128x128, BK=64, 3-stage cp.async, 8 warps (2m x 4n), warp tile 64x32.
// A: [m][k] smem, ldmatrix.  B: [k][n] smem (natural weight layout), ldmatrix.trans.
// IS1:  h[e,slot][n] = relu(sum_k x[tok][k] * w1[e][k][n]),   K=DD, Bstride=HH
// !IS1: out[tok][n] += wt * sum_k h[e,slot][k] * w2[e][k][n], K=HH, Bstride=DD
template <bool IS1>
__global__ __launch_bounds__(256, 2) void k_gemm(float* __restrict__ out) {
    const int e = blockIdx.z;
    const int m0 = blockIdx.y * 128;
    {
        int c = g_counts[e];
        if (c > CAP) c = CAP;
        int p = (c + 127) & ~127;
        if (p > CAP) p = CAP;
        if (m0 >= p) return;
    }
    const int n0 = blockIdx.x * 128;
    const int KDIM = IS1 ? DD : HH;
    const int BSTR = IS1 ? HH : DD;
    const int T = KDIM / 64;

    extern __shared__ char smem[];
    const uint32_t sb = smem_u32(smem);
    int* toks = (int*)(smem + SMEM_TOKS);
    float* wts = (float*)(smem + SMEM_WTS);
    const int tid = threadIdx.x;

    if (tid < 128) {
        toks[tid] = g_tokens[e * CAP + m0 + tid];
        if (!IS1) wts[tid] = g_wt[e * CAP + m0 + tid];
    }
    __syncthreads();

    const __half* bsrc = IS1 ? g_w1h + (size_t)e * DD * HH + n0
                             : g_w2h + (size_t)e * HH * DD + n0;
    const __half* asrc0 = g_h + (size_t)(e * CAP + m0) * HH;  // !IS1 A base

    auto issue = [&](int kt) {
        const int s = kt % NSTAGE;
        const int k0 = kt * 64;
        const uint32_t Ab = sb + s * STAGE_BYTES;
        const uint32_t Bb = Ab + 16384;
#pragma unroll
        for (int i = 0; i < 4; i++) {
            int idx = tid + 256 * i;
            int row = idx >> 3, c = idx & 7;
            const __half* sa = IS1 ? g_xh + (size_t)toks[row] * DD + k0 + c * 8
                                   : asrc0 + (size_t)row * HH + k0 + c * 8;
            cp_async16(Ab + row * 128 + ((c ^ (row & 7)) << 4), sa);
        }
#pragma unroll
        for (int i = 0; i < 4; i++) {
            int idx = tid + 256 * i;
            int row = idx >> 4, c = idx & 15;
            cp_async16(Bb + row * 256 + ((c ^ (row & 7)) << 4),
                       bsrc + (size_t)(k0 + row) * BSTR + c * 8);
        }
    };

    issue(0); cp_commit();
    issue(1); cp_commit();

    const int lane = tid & 31, wid = tid >> 5;
    const int wm = wid & 1, wn = wid >> 1;  // 2m x 4n warps, 64x32 each
    const int lrow = lane & 15, lk = lane >> 4;

    float acc[4][4][4];
#pragma unroll
    for (int a = 0; a < 4; a++)
#pragma unroll
        for (int b = 0; b < 4; b++)
#pragma unroll
            for (int c = 0; c < 4; c++) acc[a][b][c] = 0.f;

    for (int kt = 0; kt < T; kt++) {
        cp_wait1();
        __syncthreads();
        if (kt + 2 < T) issue(kt + 2);
        cp_commit();

        const uint32_t Ab = sb + (kt % NSTAGE) * STAGE_BYTES;
        const uint32_t Bb = Ab + 16384;
#pragma unroll
        for (int ks = 0; ks < 4; ks++) {
            uint32_t a[4][4], b[2][4];
#pragma unroll
            for (int mt = 0; mt < 4; mt++) {
                int row = wm * 64 + mt * 16 + lrow;
                ldsm4(a[mt], Ab + row * 128 + ((((ks << 1) | lk) ^ (row & 7)) << 4));
            }
#pragma unroll
            for (int nt2 = 0; nt2 < 2; nt2++) {
                int krow = ks * 16 + lrow;
                int chunk = wn * 4 + nt2 * 2 + lk;
                ldsm4t(b[nt2], Bb + krow * 256 + ((chunk ^ (krow & 7)) << 4));
            }
#pragma unroll
            for (int mt = 0; mt < 4; mt++)
#pragma unroll
                for (int nt = 0; nt < 4; nt++) {
                    const int nt2 = nt >> 1, sub = nt & 1;
                    mma16816(acc[mt][nt], a[mt], b[nt2][2 * sub], b[nt2][2 * sub + 1]);
                }
        }
    }

    // epilogue
    const int g = lane >> 2, tg = lane & 3;
    if (IS1) {
#pragma unroll
        for (int mt = 0; mt < 4; mt++) {
            const size_t r0 = (size_t)(e * CAP + m0 + wm * 64 + mt * 16 + g);
            __half* p0 = g_h + r0 * HH + n0;
            __half* p1 = p0 + (size_t)8 * HH;
#pragma unroll
            for (int nt = 0; nt < 4; nt++) {
                const int c = wn * 32 + nt * 8 + tg * 2;
                const float* A = acc[mt][nt];
                *(__half2*)(p0 + c) = __floats2half2_rn(fmaxf(A[0], 0.f), fmaxf(A[1], 0.f));
                *(__half2*)(p1 + c) = __floats2half2_rn(fmaxf(A[2], 0.f), fmaxf(A[3], 0.f));
            }
        }
    } else {
#pragma unroll
        for (int mt = 0; mt < 4; mt++) {
            const int rl = wm * 64 + mt * 16 + g;
            const int t0 = toks[rl];
            const float w0 = wts[rl];
            const int t1 = toks[rl + 8];
            const float w1v = wts[rl + 8];
            float* o0 = out + (size_t)t0 * DD + n0;
            float* o1 = out + (size_t)t1 * DD + n0;
#pragma unroll
            for (int nt = 0; nt < 4; nt++) {
                const int c = wn * 32 + nt * 8 + tg * 2;
                const float* A = acc[mt][nt];
                atomicAdd(o0 + c,     w0 * A[0]);
                atomicAdd(o0 + c + 1, w0 * A[1]);
                atomicAdd(o1 + c,     w1v * A[2]);
                atomicAdd(o1 + c + 1, w1v * A[3]);
            }
        }
    }
}

extern "C" void kernel_launch(void* const* d_in, const int* in_sizes, int n_in,
                              void* d_out, int out_size) {
    const float* xs = (const float*)d_in[0];
    const float* gw = (const float*)d_in[1];
    const float* w1 = (const float*)d_in[2];
    const float* w2 = (const float*)d_in[3];
    float* out = (float*)d_out;

    cudaFuncSetAttribute(k_gemm<true>, cudaFuncAttributeMaxDynamicSharedMemorySize, SMEM_SZ);
    cudaFuncSetAttribute(k_gemm<false>, cudaFuncAttributeMaxDynamicSharedMemorySize, SMEM_SZ);

    // launch #1: zero out + token lists + weights + counters
    k_zero<<<2048, 256>>>(out);
    // launch #2: convert x, w1, w2 to fp16 in one pass
    k_cvt_all<<<(int)((NX + 2 * NW) / 8 / 256), 256>>>(xs, w1, w2);
    // launch #3: router
    k_router<<<NTOK / 8, 256>>>(xs, gw);
    // launch #4: gemm1  (ncu capture slot)
    k_gemm<true><<<dim3(HH / 128, CAP / 128, EE), 256, SMEM_SZ>>>(out);
    // launch #5: gemm2
    k_gemm<false><<<dim3(DD / 128, CAP / 128, EE), 256, SMEM_SZ>>>(out);
}

// round 9
// speedup vs baseline: 1.3201x; 1.0104x over previous
#include <cuda_runtime.h>
#include <cuda_fp16.h>
#include <cstdint>
#include <cstddef>

#define DD   1024
#define HH   4096
#define EE   8
#define NTOK 8192
#define CAP  8192
#define NSTAGE 3
#define STAGE_BYTES 32768            // 16KB A (128m x 64k) + 16KB B (64k x 128n)
#define SMEM_TOKS (NSTAGE * STAGE_BYTES)
#define SMEM_SZ   (SMEM_TOKS + 512)

#define NX ((size_t)NTOK * DD)       // 8388608
#define NW ((size_t)EE * DD * HH)    // 33554432

// ---- device scratch (static: no runtime allocation) ----
__device__ int    g_counts[EE];
__device__ int    g_tokens[EE * CAP];
__device__ int    g_slot[NTOK * 2];
__device__ float  g_swt[NTOK * 2];
__device__ __half g_xh[NX];                         // x fp16, 16MB
__device__ __half g_w1h[NW];                        // w1 fp16 [e][d][h], 64MB
__device__ __half g_w2h[NW];                        // w2 fp16 [e][h][d], 64MB
__device__ __half g_h[(size_t)EE * CAP * HH];       // relu(h) fp16, 128MB (sparse use)
__device__ float  g_y[(size_t)EE * CAP * DD];       // per-slot y fp32, 256MB (sparse use)

// ---- helpers ----
__device__ __forceinline__ uint32_t smem_u32(const void* p) {
    uint32_t a;
    asm("{ .reg .u64 t; cvta.to.shared.u64 t, %1; cvt.u32.u64 %0, t; }" : "=r"(a) : "l"(p));
    return a;
}
__device__ __forceinline__ void cp_async16(uint32_t dst, const void* src) {
    asm volatile("cp.async.cg.shared.global [%0], [%1], 16;" :: "r"(dst), "l"(src) : "memory");
}
__device__ __forceinline__ void cp_commit() {
    asm volatile("cp.async.commit_group;" ::: "memory");
}
__device__ __forceinline__ void cp_wait1() {
    asm volatile("cp.async.wait_group 1;" ::: "memory");
}
__device__ __forceinline__ void ldsm4(uint32_t r[4], uint32_t addr) {
    asm volatile("ldmatrix.sync.aligned.m8n8.x4.shared.b16 {%0,%1,%2,%3}, [%4];"
                 : "=r"(r[0]), "=r"(r[1]), "=r"(r[2]), "=r"(r[3]) : "r"(addr));
}
__device__ __forceinline__ void ldsm4t(uint32_t r[4], uint32_t addr) {
    asm volatile("ldmatrix.sync.aligned.m8n8.x4.trans.shared.b16 {%0,%1,%2,%3}, [%4];"
                 : "=r"(r[0]), "=r"(r[1]), "=r"(r[2]), "=r"(r[3]) : "r"(addr));
}
__device__ __forceinline__ void mma16816(float c[4], const uint32_t a[4], uint32_t b0, uint32_t b1) {
    asm volatile(
        "mma.sync.aligned.m16n8k16.row.col.f32.f16.f16.f32 "
        "{%0,%1,%2,%3},{%4,%5,%6,%7},{%8,%9},{%0,%1,%2,%3};"
        : "+f"(c[0]), "+f"(c[1]), "+f"(c[2]), "+f"(c[3])
        : "r"(a[0]), "r"(a[1]), "r"(a[2]), "r"(a[3]), "r"(b0), "r"(b1));
}

// ---- launch 1: fp32->fp16 convert of x,w1,w2 + zero token lists/counters ----
__global__ void k_prep(const float* __restrict__ xs, const float* __restrict__ w1,
                       const float* __restrict__ w2) {
    size_t i = ((size_t)blockIdx.x * blockDim.x + threadIdx.x) * 8;
    const float* src;
    __half* dst;
    size_t off;
    if (i < NX)            { src = xs; dst = g_xh;  off = i; }
    else if (i < NX + NW)  { src = w1; dst = g_w1h; off = i - NX; }
    else                   { src = w2; dst = g_w2h; off = i - NX - NW; }
    float4 a = *reinterpret_cast<const float4*>(src + off);
    float4 b = *reinterpret_cast<const float4*>(src + off + 4);
    __half2 h[4];
    h[0] = __floats2half2_rn(a.x, a.y);
    h[1] = __floats2half2_rn(a.z, a.w);
    h[2] = __floats2half2_rn(b.x, b.y);
    h[3] = __floats2half2_rn(b.z, b.w);
    *reinterpret_cast<uint4*>(dst + off) = *reinterpret_cast<uint4*>(h);

    // zero token lists (EE*CAP ints = 16384 int4) + counters
    if (blockIdx.x < 64) {
        int j = blockIdx.x * 256 + threadIdx.x;
        reinterpret_cast<int4*>(g_tokens)[j] = make_int4(0, 0, 0, 0);
        if (blockIdx.x == 0 && threadIdx.x < EE) g_counts[threadIdx.x] = 0;
    }
}

// ---- launch 2: router (1 warp per token, fp32 selection) ----
__global__ void k_router(const float* __restrict__ xs, const float* __restrict__ gw) {
    int warp = (int)((blockIdx.x * blockDim.x + threadIdx.x) >> 5);
    int lane = threadIdx.x & 31;
    if (warp >= NTOK) return;

    const float* x = xs + (size_t)warp * DD;
    float xr[32];
#pragma unroll
    for (int i = 0; i < 32; i++) xr[i] = x[lane + 32 * i];

    float logit[EE];
#pragma unroll
    for (int e = 0; e < EE; e++) {
        const float* g = gw + e * DD;
        float a = 0.f;
#pragma unroll
        for (int i = 0; i < 32; i++) a += xr[i] * g[lane + 32 * i];
#pragma unroll
        for (int o = 16; o; o >>= 1) a += __shfl_xor_sync(0xFFFFFFFFu, a, o);
        logit[e] = a;
    }

    if (lane == 0) {
        float v0 = -1e30f, v1 = -1e30f;
        int i0 = 0, i1 = 0;
#pragma unroll
        for (int e = 0; e < EE; e++) {
            float v = logit[e];
            if (v > v0) { v1 = v0; i1 = i0; v0 = v; i0 = e; }
            else if (v > v1) { v1 = v; i1 = e; }
        }
        float e1 = __expf(v1 - v0);
        float s = 1.f + e1;
        float w0 = 1.f / s;
        float w1 = e1 / s;

        int s0 = atomicAdd(&g_counts[i0], 1);
        g_tokens[i0 * CAP + s0] = warp;
        g_slot[warp * 2 + 0] = i0 * CAP + s0;
        g_swt[warp * 2 + 0] = w0;
        int s1 = atomicAdd(&g_counts[i1], 1);
        g_tokens[i1 * CAP + s1] = warp;
        g_slot[warp * 2 + 1] = i1 * CAP + s1;
        g_swt[warp * 2 + 1] = w1;
    }
}

// ---- fp16 tensor-core grouped GEMM ----
// CTA tile 128x128, BK=64, 3-stage cp.async, 8 warps (2m x 4n), warp tile 64x32.
// A: [m][k] smem, ldmatrix.  B: [k][n] smem (natural weight layout), ldmatrix.trans.
// IS1:  h[e,slot][n] = relu(sum_k x[tok][k] * w1[e][k][n]),   K=DD
// !IS1: y[e,slot][n] = sum_k h[e,slot][k] * w2[e][k][n],      K=HH  (plain stores)
template <bool IS1>
__global__ __launch_bounds__(256, 2) void k_gemm() {
    const int e = blockIdx.z;
    const int m0 = blockIdx.y * 128;
    {
        int c = g_counts[e];
        if (c > CAP) c = CAP;
        int p = (c + 127) & ~127;
        if (p > CAP) p = CAP;
        if (m0 >= p) return;
    }
    const int n0 = blockIdx.x * 128;
    const int KDIM = IS1 ? DD : HH;
    const int BSTR = IS1 ? HH : DD;
    const int T = KDIM / 64;

    extern __shared__ char smem[];
    const uint32_t sb = smem_u32(smem);
    int* toks = (int*)(smem + SMEM_TOKS);
    const int tid = threadIdx.x;

    if (IS1 && tid < 128) toks[tid] = g_tokens[e * CAP + m0 + tid];
    __syncthreads();

    const __half* bsrc = IS1 ? g_w1h + (size_t)e * DD * HH + n0
                             : g_w2h + (size_t)e * HH * DD + n0;
    const __half* asrc0 = g_h + (size_t)(e * CAP + m0) * HH;  // !IS1 A base

    auto issue = [&](int kt) {
        const int s = kt % NSTAGE;
        const int k0 = kt * 64;
        const uint32_t Ab = sb + s * STAGE_BYTES;
        const uint32_t Bb = Ab + 16384;
#pragma unroll
        for (int i = 0; i < 4; i++) {
            int idx = tid + 256 * i;
            int row = idx >> 3, c = idx & 7;
            const __half* sa = IS1 ? g_xh + (size_t)toks[row] * DD + k0 + c * 8
                                   : asrc0 + (size_t)row * HH + k0 + c * 8;
            cp_async16(Ab + row * 128 + ((c ^ (row & 7)) << 4), sa);
        }
#pragma unroll
        for (int i = 0; i < 4; i++) {
            int idx = tid + 256 * i;
            int row = idx >> 4, c = idx & 15;
            cp_async16(Bb + row * 256 + ((c ^ (row & 7)) << 4),
                       bsrc + (size_t)(k0 + row) * BSTR + c * 8);
        }
    };

    issue(0); cp_commit();
    issue(1); cp_commit();

    const int lane = tid & 31, wid = tid >> 5;
    const int wm = wid & 1, wn = wid >> 1;  // 2m x 4n warps, 64x32 each
    const int lrow = lane & 15, lk = lane >> 4;

    float acc[4][4][4];
#pragma unroll
    for (int a = 0; a < 4; a++)
#pragma unroll
        for (int b = 0; b < 4; b++)
#pragma unroll
            for (int c = 0; c < 4; c++) acc[a][b][c] = 0.f;

    for (int kt = 0; kt < T; kt++) {
        cp_wait1();
        __syncthreads();
        if (kt + 2 < T) issue(kt + 2);
        cp_commit();

        const uint32_t Ab = sb + (kt % NSTAGE) * STAGE_BYTES;
        const uint32_t Bb = Ab + 16384;
#pragma unroll
        for (int ks = 0; ks < 4; ks++) {
            uint32_t a[4][4], b[2][4];
#pragma unroll
            for (int mt = 0; mt < 4; mt++) {
                int row = wm * 64 + mt * 16 + lrow;
                ldsm4(a[mt], Ab + row * 128 + ((((ks << 1) | lk) ^ (row & 7)) << 4));
            }
#pragma unroll
            for (int nt2 = 0; nt2 < 2; nt2++) {
                int krow = ks * 16 + lrow;
                int chunk = wn * 4 + nt2 * 2 + lk;
                ldsm4t(b[nt2], Bb + krow * 256 + ((chunk ^ (krow & 7)) << 4));
            }
#pragma unroll
            for (int mt = 0; mt < 4; mt++)
#pragma unroll
                for (int nt = 0; nt < 4; nt++) {
                    const int nt2 = nt >> 1, sub = nt & 1;
                    mma16816(acc[mt][nt], a[mt], b[nt2][2 * sub], b[nt2][2 * sub + 1]);
                }
        }
    }

    // epilogue (no atomics)
    const int g = lane >> 2, tg = lane & 3;
    if (IS1) {
#pragma unroll
        for (int mt = 0; mt < 4; mt++) {
            const size_t r0 = (size_t)(e * CAP + m0 + wm * 64 + mt * 16 + g);
            __half* p0 = g_h + r0 * HH + n0;
            __half* p1 = p0 + (size_t)8 * HH;
#pragma unroll
            for (int nt = 0; nt < 4; nt++) {
                const int c = wn * 32 + nt * 8 + tg * 2;
                const float* A = acc[mt][nt];
                *(__half2*)(p0 + c) = __floats2half2_rn(fmaxf(A[0], 0.f), fmaxf(A[1], 0.f));
                *(__half2*)(p1 + c) = __floats2half2_rn(fmaxf(A[2], 0.f), fmaxf(A[3], 0.f));
            }
        }
    } else {
#pragma unroll
        for (int mt = 0; mt < 4; mt++) {
            const size_t r0 = (size_t)(e * CAP + m0 + wm * 64 + mt * 16 + g);
            float* y0 = g_y + r0 * DD + n0;
            float* y1 = y0 + (size_t)8 * DD;
#pragma unroll
            for (int nt = 0; nt < 4; nt++) {
                const int c = wn * 32 + nt * 8 + tg * 2;
                const float* A = acc[mt][nt];
                *(float2*)(y0 + c) = make_float2(A[0], A[1]);
                *(float2*)(y1 + c) = make_float2(A[2], A[3]);
            }
        }
    }
}

// ---- launch 5: combine  out[t] = w0*y[s0] + w1*y[s1]  (fully writes out) ----
__global__ __launch_bounds__(256) void k_combine(float* __restrict__ out) {
    const int t = blockIdx.x;
    const int s0 = g_slot[t * 2 + 0];
    const int s1 = g_slot[t * 2 + 1];
    const float w0 = g_swt[t * 2 + 0];
    const float w1 = g_swt[t * 2 + 1];
    const float4 a = ((const float4*)(g_y + (size_t)s0 * DD))[threadIdx.x];
    const float4 b = ((const float4*)(g_y + (size_t)s1 * DD))[threadIdx.x];
    float4 o;
    o.x = w0 * a.x + w1 * b.x;
    o.y = w0 * a.y + w1 * b.y;
    o.z = w0 * a.z + w1 * b.z;
    o.w = w0 * a.w + w1 * b.w;
    ((float4*)(out + (size_t)t * DD))[threadIdx.x] = o;
}

extern "C" void kernel_launch(void* const* d_in, const int* in_sizes, int n_in,
                              void* d_out, int out_size) {
    const float* xs = (const float*)d_in[0];
    const float* gw = (const float*)d_in[1];
    const float* w1 = (const float*)d_in[2];
    const float* w2 = (const float*)d_in[3];
    float* out = (float*)d_out;

    cudaFuncSetAttribute(k_gemm<true>, cudaFuncAttributeMaxDynamicSharedMemorySize, SMEM_SZ);
    cudaFuncSetAttribute(k_gemm<false>, cudaFuncAttributeMaxDynamicSharedMemorySize, SMEM_SZ);

    // launch #1: convert x,w1,w2 + zero token lists/counters
    k_prep<<<(int)((NX + 2 * NW) / 8 / 256), 256>>>(xs, w1, w2);
    // launch #2: router (records slots + softmax weights per token)
    k_router<<<NTOK / 8, 256>>>(xs, gw);
    // launch #3: gemm1
    k_gemm<true><<<dim3(HH / 128, CAP / 128, EE), 256, SMEM_SZ>>>();
    // launch #4: gemm2 (ncu capture slot — first gemm2 profile)
    k_gemm<false><<<dim3(DD / 128, CAP / 128, EE), 256, SMEM_SZ>>>();
    // launch #5: combine into out
    k_combine<<<NTOK, 256>>>(out);
}

// round 11
// speedup vs baseline: 1.3385x; 1.0140x over previous
#include <cuda_runtime.h>
#include <cuda_fp16.h>
#include <cstdint>
#include <cstddef>

#define DD   1024
#define HH   4096
#define EE   8
#define NTOK 8192
#define CAP  8192
#define NSTAGE 3
#define STAGE_BYTES 32768            // 16KB A (128m x 64k) + 16KB B (64k x 128n)
#define SMEM_TOKS (NSTAGE * STAGE_BYTES)
#define SMEM_SZ   (SMEM_TOKS + 512)

#define NX ((size_t)NTOK * DD)       // 8388608
#define NW ((size_t)EE * DD * HH)    // 33554432

// ---- device scratch (static: no runtime allocation) ----
__device__ int    g_counts[EE];
__device__ int    g_tokens[EE * CAP];
__device__ int    g_slot[NTOK * 2];
__device__ float  g_swt[NTOK * 2];
__device__ __half g_xh[NX];                         // x fp16, 16MB
__device__ __half g_w1h[NW];                        // w1 fp16 [e][d][h], 64MB
__device__ __half g_w2h[NW];                        // w2 fp16 [e][h][d], 64MB
__device__ __half g_h[(size_t)EE * CAP * HH];       // relu(h) fp16, 128MB (sparse use)
__device__ float  g_y[(size_t)EE * CAP * DD];       // per-slot y fp32, 256MB (sparse use)

// ---- helpers ----
__device__ __forceinline__ uint32_t smem_u32(const void* p) {
    uint32_t a;
    asm("{ .reg .u64 t; cvta.to.shared.u64 t, %1; cvt.u32.u64 %0, t; }" : "=r"(a) : "l"(p));
    return a;
}
__device__ __forceinline__ void cp_async16(uint32_t dst, const void* src) {
    asm volatile("cp.async.cg.shared.global [%0], [%1], 16;" :: "r"(dst), "l"(src) : "memory");
}
__device__ __forceinline__ void cp_commit() {
    asm volatile("cp.async.commit_group;" ::: "memory");
}
__device__ __forceinline__ void cp_wait1() {
    asm volatile("cp.async.wait_group 1;" ::: "memory");
}
__device__ __forceinline__ void ldsm4(uint32_t r[4], uint32_t addr) {
    asm volatile("ldmatrix.sync.aligned.m8n8.x4.shared.b16 {%0,%1,%2,%3}, [%4];"
                 : "=r"(r[0]), "=r"(r[1]), "=r"(r[2]), "=r"(r[3]) : "r"(addr));
}
__device__ __forceinline__ void ldsm4t(uint32_t r[4], uint32_t addr) {
    asm volatile("ldmatrix.sync.aligned.m8n8.x4.trans.shared.b16 {%0,%1,%2,%3}, [%4];"
                 : "=r"(r[0]), "=r"(r[1]), "=r"(r[2]), "=r"(r[3]) : "r"(addr));
}
__device__ __forceinline__ void mma16816(float c[4], const uint32_t a[4], uint32_t b0, uint32_t b1) {
    asm volatile(
        "mma.sync.aligned.m16n8k16.row.col.f32.f16.f16.f32 "
        "{%0,%1,%2,%3},{%4,%5,%6,%7},{%8,%9},{%0,%1,%2,%3};"
        : "+f"(c[0]), "+f"(c[1]), "+f"(c[2]), "+f"(c[3])
        : "r"(a[0]), "r"(a[1]), "r"(a[2]), "r"(a[3]), "r"(b0), "r"(b1));
}

// ---- zero token lists + counters (router branch, BEFORE router: no race) ----
__global__ void k_zero_lists() {
    int j = blockIdx.x * 256 + threadIdx.x;          // 64 blocks x 256 = 16384 int4
    reinterpret_cast<int4*>(g_tokens)[j] = make_int4(0, 0, 0, 0);
    if (blockIdx.x == 0 && threadIdx.x < EE) g_counts[threadIdx.x] = 0;
}

// ---- fp32->fp16 convert of x,w1 (main stream) ----
__global__ void k_prep_xw1(const float* __restrict__ xs, const float* __restrict__ w1) {
    size_t i = ((size_t)blockIdx.x * blockDim.x + threadIdx.x) * 8;
    const float* src;
    __half* dst;
    size_t off;
    if (i < NX) { src = xs; dst = g_xh;  off = i; }
    else        { src = w1; dst = g_w1h; off = i - NX; }
    float4 a = *reinterpret_cast<const float4*>(src + off);
    float4 b = *reinterpret_cast<const float4*>(src + off + 4);
    __half2 h[4];
    h[0] = __floats2half2_rn(a.x, a.y);
    h[1] = __floats2half2_rn(a.z, a.w);
    h[2] = __floats2half2_rn(b.x, b.y);
    h[3] = __floats2half2_rn(b.z, b.w);
    *reinterpret_cast<uint4*>(dst + off) = *reinterpret_cast<uint4*>(h);
}

// ---- fp32->fp16 convert of w2 (parallel branch; only needed by gemm2) ----
__global__ void k_prep_w2(const float* __restrict__ w2) {
    size_t i = ((size_t)blockIdx.x * blockDim.x + threadIdx.x) * 8;
    float4 a = *reinterpret_cast<const float4*>(w2 + i);
    float4 b = *reinterpret_cast<const float4*>(w2 + i + 4);
    __half2 h[4];
    h[0] = __floats2half2_rn(a.x, a.y);
    h[1] = __floats2half2_rn(a.z, a.w);
    h[2] = __floats2half2_rn(b.x, b.y);
    h[3] = __floats2half2_rn(b.z, b.w);
    *reinterpret_cast<uint4*>(g_w2h + i) = *reinterpret_cast<uint4*>(h);
}

// ---- router (1 warp per token, fp32 selection); reads only raw inputs ----
__global__ void k_router(const float* __restrict__ xs, const float* __restrict__ gw) {
    int warp = (int)((blockIdx.x * blockDim.x + threadIdx.x) >> 5);
    int lane = threadIdx.x & 31;
    if (warp >= NTOK) return;

    const float* x = xs + (size_t)warp * DD;
    float xr[32];
#pragma unroll
    for (int i = 0; i < 32; i++) xr[i] = x[lane + 32 * i];

    float logit[EE];
#pragma unroll
    for (int e = 0; e < EE; e++) {
        const float* g = gw + e * DD;
        float a = 0.f;
#pragma unroll
        for (int i = 0; i < 32; i++) a += xr[i] * g[lane + 32 * i];
#pragma unroll
        for (int o = 16; o; o >>= 1) a += __shfl_xor_sync(0xFFFFFFFFu, a, o);
        logit[e] = a;
    }

    if (lane == 0) {
        float v0 = -1e30f, v1 = -1e30f;
        int i0 = 0, i1 = 0;
#pragma unroll
        for (int e = 0; e < EE; e++) {
            float v = logit[e];
            if (v > v0) { v1 = v0; i1 = i0; v0 = v; i0 = e; }
            else if (v > v1) { v1 = v; i1 = e; }
        }
        float e1 = __expf(v1 - v0);
        float s = 1.f + e1;
        float w0 = 1.f / s;
        float w1 = e1 / s;

        int s0 = atomicAdd(&g_counts[i0], 1);
        g_tokens[i0 * CAP + s0] = warp;
        g_slot[warp * 2 + 0] = i0 * CAP + s0;
        g_swt[warp * 2 + 0] = w0;
        int s1 = atomicAdd(&g_counts[i1], 1);
        g_tokens[i1 * CAP + s1] = warp;
        g_slot[warp * 2 + 1] = i1 * CAP + s1;
        g_swt[warp * 2 + 1] = w1;
    }
}

// ---- fp16 tensor-core grouped GEMM ----
// CTA tile 128x128, BK=64, 3-stage cp.async, 8 warps (2m x 4n), warp tile 64x32.
// IS1:  h[e,slot][n] = relu(sum_k x[tok][k] * w1[e][k][n]),   K=DD
// !IS1: y[e,slot][n] = sum_k h[e,slot][k] * w2[e][k][n],      K=HH  (plain stores)
template <bool IS1>
__global__ __launch_bounds__(256, 2) void k_gemm() {
    const int e = blockIdx.z;
    const int m0 = blockIdx.y * 128;
    {
        int c = g_counts[e];
        if (c > CAP) c = CAP;
        int p = (c + 127) & ~127;
        if (p > CAP) p = CAP;
        if (m0 >= p) return;
    }
    const int n0 = blockIdx.x * 128;
    const int KDIM = IS1 ? DD : HH;
    const int BSTR = IS1 ? HH : DD;
    const int T = KDIM / 64;

    extern __shared__ char smem[];
    const uint32_t sb = smem_u32(smem);
    int* toks = (int*)(smem + SMEM_TOKS);
    const int tid = threadIdx.x;

    if (IS1 && tid < 128) toks[tid] = g_tokens[e * CAP + m0 + tid];
    __syncthreads();

    const __half* bsrc = IS1 ? g_w1h + (size_t)e * DD * HH + n0
                             : g_w2h + (size_t)e * HH * DD + n0;
    const __half* asrc0 = g_h + (size_t)(e * CAP + m0) * HH;  // !IS1 A base

    auto issue = [&](int kt) {
        const int s = kt % NSTAGE;
        const int k0 = kt * 64;
        const uint32_t Ab = sb + s * STAGE_BYTES;
        const uint32_t Bb = Ab + 16384;
#pragma unroll
        for (int i = 0; i < 4; i++) {
            int idx = tid + 256 * i;
            int row = idx >> 3, c = idx & 7;
            const __half* sa = IS1 ? g_xh + (size_t)toks[row] * DD + k0 + c * 8
                                   : asrc0 + (size_t)row * HH + k0 + c * 8;
            cp_async16(Ab + row * 128 + ((c ^ (row & 7)) << 4), sa);
        }
#pragma unroll
        for (int i = 0; i < 4; i++) {
            int idx = tid + 256 * i;
            int row = idx >> 4, c = idx & 15;
            cp_async16(Bb + row * 256 + ((c ^ (row & 7)) << 4),
                       bsrc + (size_t)(k0 + row) * BSTR + c * 8);
        }
    };

    issue(0); cp_commit();
    issue(1); cp_commit();

    const int lane = tid & 31, wid = tid >> 5;
    const int wm = wid & 1, wn = wid >> 1;  // 2m x 4n warps, 64x32 each
    const int lrow = lane & 15, lk = lane >> 4;

    float acc[4][4][4];
#pragma unroll
    for (int a = 0; a < 4; a++)
#pragma unroll
        for (int b = 0; b < 4; b++)
#pragma unroll
            for (int c = 0; c < 4; c++) acc[a][b][c] = 0.f;

    for (int kt = 0; kt < T; kt++) {
        cp_wait1();
        __syncthreads();
        if (kt + 2 < T) issue(kt + 2);
        cp_commit();

        const uint32_t Ab = sb + (kt % NSTAGE) * STAGE_BYTES;
        const uint32_t Bb = Ab + 16384;
#pragma unroll
        for (int ks = 0; ks < 4; ks++) {
            uint32_t a[4][4], b[2][4];
#pragma unroll
            for (int mt = 0; mt < 4; mt++) {
                int row = wm * 64 + mt * 16 + lrow;
                ldsm4(a[mt], Ab + row * 128 + ((((ks << 1) | lk) ^ (row & 7)) << 4));
            }
#pragma unroll
            for (int nt2 = 0; nt2 < 2; nt2++) {
                int krow = ks * 16 + lrow;
                int chunk = wn * 4 + nt2 * 2 + lk;
                ldsm4t(b[nt2], Bb + krow * 256 + ((chunk ^ (krow & 7)) << 4));
            }
#pragma unroll
            for (int mt = 0; mt < 4; mt++)
#pragma unroll
                for (int nt = 0; nt < 4; nt++) {
                    const int nt2 = nt >> 1, sub = nt & 1;
                    mma16816(acc[mt][nt], a[mt], b[nt2][2 * sub], b[nt2][2 * sub + 1]);
                }
        }
    }

    // epilogue (no atomics)
    const int g = lane >> 2, tg = lane & 3;
    if (IS1) {
#pragma unroll
        for (int mt = 0; mt < 4; mt++) {
            const size_t r0 = (size_t)(e * CAP + m0 + wm * 64 + mt * 16 + g);
            __half* p0 = g_h + r0 * HH + n0;
            __half* p1 = p0 + (size_t)8 * HH;
#pragma unroll
            for (int nt = 0; nt < 4; nt++) {
                const int c = wn * 32 + nt * 8 + tg * 2;
                const float* A = acc[mt][nt];
                *(__half2*)(p0 + c) = __floats2half2_rn(fmaxf(A[0], 0.f), fmaxf(A[1], 0.f));
                *(__half2*)(p1 + c) = __floats2half2_rn(fmaxf(A[2], 0.f), fmaxf(A[3], 0.f));
            }
        }
    } else {
#pragma unroll
        for (int mt = 0; mt < 4; mt++) {
            const size_t r0 = (size_t)(e * CAP + m0 + wm * 64 + mt * 16 + g);
            float* y0 = g_y + r0 * DD + n0;
            float* y1 = y0 + (size_t)8 * DD;
#pragma unroll
            for (int nt = 0; nt < 4; nt++) {
                const int c = wn * 32 + nt * 8 + tg * 2;
                const float* A = acc[mt][nt];
                *(float2*)(y0 + c) = make_float2(A[0], A[1]);
                *(float2*)(y1 + c) = make_float2(A[2], A[3]);
            }
        }
    }
}

// ---- combine: out[t] = w0*y[s0] + w1*y[s1]  (fully writes out) ----
__global__ __launch_bounds__(256) void k_combine(float* __restrict__ out) {
    const int t = blockIdx.x;
    const int s0 = g_slot[t * 2 + 0];
    const int s1 = g_slot[t * 2 + 1];
    const float w0 = g_swt[t * 2 + 0];
    const float w1 = g_swt[t * 2 + 1];
    const float4 a = ((const float4*)(g_y + (size_t)s0 * DD))[threadIdx.x];
    const float4 b = ((const float4*)(g_y + (size_t)s1 * DD))[threadIdx.x];
    float4 o;
    o.x = w0 * a.x + w1 * b.x;
    o.y = w0 * a.y + w1 * b.y;
    o.z = w0 * a.z + w1 * b.z;
    o.w = w0 * a.w + w1 * b.w;
    ((float4*)(out + (size_t)t * DD))[threadIdx.x] = o;
}

extern "C" void kernel_launch(void* const* d_in, const int* in_sizes, int n_in,
                              void* d_out, int out_size) {
    const float* xs = (const float*)d_in[0];
    const float* gw = (const float*)d_in[1];
    const float* w1 = (const float*)d_in[2];
    const float* w2 = (const float*)d_in[3];
    float* out = (float*)d_out;

    // one-time host-side setup (first call is the uncaptured correctness run)
    static cudaStream_t sW2 = nullptr, sRT = nullptr;
    static cudaEvent_t evRoot = nullptr, evW2 = nullptr, evRT = nullptr;
    if (!sW2) {
        cudaStreamCreateWithFlags(&sW2, cudaStreamNonBlocking);
        cudaStreamCreateWithFlags(&sRT, cudaStreamNonBlocking);
        cudaEventCreateWithFlags(&evRoot, cudaEventDisableTiming);
        cudaEventCreateWithFlags(&evW2, cudaEventDisableTiming);
        cudaEventCreateWithFlags(&evRT, cudaEventDisableTiming);
        cudaFuncSetAttribute(k_gemm<true>, cudaFuncAttributeMaxDynamicSharedMemorySize, SMEM_SZ);
        cudaFuncSetAttribute(k_gemm<false>, cudaFuncAttributeMaxDynamicSharedMemorySize, SMEM_SZ);
    }

    // fork: branch streams hang off the capture-origin (default) stream
    cudaEventRecord(evRoot, 0);
    cudaStreamWaitEvent(sW2, evRoot, 0);
    cudaStreamWaitEvent(sRT, evRoot, 0);

    // branch RT: zero lists/counters THEN router (same stream -> ordered, no race)
    k_zero_lists<<<64, 256, 0, sRT>>>();
    k_router<<<NTOK / 8, 256, 0, sRT>>>(xs, gw);
    cudaEventRecord(evRT, sRT);

    // branch W2: w2 conversion (needed only by gemm2; overlaps prep_xw1 + gemm1)
    k_prep_w2<<<(int)(NW / 8 / 256), 256, 0, sW2>>>(w2);
    cudaEventRecord(evW2, sW2);

    // main: x+w1 conversion, then gemm1 (after router), gemm2 (after w2), combine
    k_prep_xw1<<<(int)((NX + NW) / 8 / 256), 256>>>(xs, w1);
    cudaStreamWaitEvent(0, evRT, 0);
    k_gemm<true><<<dim3(HH / 128, CAP / 128, EE), 256, SMEM_SZ>>>();
    cudaStreamWaitEvent(0, evW2, 0);
    k_gemm<false><<<dim3(DD / 128, CAP / 128, EE), 256, SMEM_SZ>>>();
    k_combine<<<NTOK, 256>>>(out);
}